// round 15
// baseline (speedup 1.0000x reference)
#include <cuda_runtime.h>
#include <cuda_fp16.h>
#include <math.h>
#include <stddef.h>
#include <stdint.h>

// Problem constants (B=1)
#define SEQ   2048
#define HID   2048
#define NHEADS 16
#define NKVH   4
#define DHEAD  128
#define KVW   (NKVH * DHEAD)      // 512
#define GQA_REP (NHEADS / NKVH)   // 4

// fp16 scratch
__device__ __half g_xh [SEQ * HID];
__device__ __half g_wqh[HID * HID];
__device__ __half g_wkh[KVW * HID];
__device__ __half g_wvh[KVW * HID];
__device__ __half g_woh[HID * HID];
__device__ __half g_qh [SEQ * HID];
__device__ __half g_kh [SEQ * KVW];
__device__ __half g_vh [SEQ * KVW];
__device__ __half g_ctxh[SEQ * HID];

// ---------------------------------------------------------------------------
// helpers
// ---------------------------------------------------------------------------
__device__ __forceinline__ float ex2(float x) {
    float y;
    asm("ex2.approx.ftz.f32 %0, %1;" : "=f"(y) : "f"(x));
    return y;
}
__device__ __forceinline__ float exp2poly(float x) {
    const float MAGIC = 12582912.f;
    float t = fmaxf(x, -126.f);
    float r = t + MAGIC;
    float n = r - MAGIC;
    float f = t - n;
    float p = 1.3333558146e-3f;
    p = fmaf(p, f, 9.6181291076e-3f);
    p = fmaf(p, f, 5.5504108664e-2f);
    p = fmaf(p, f, 2.4022650696e-1f);
    p = fmaf(p, f, 6.9314718056e-1f);
    p = fmaf(p, f, 1.0f);
    int sb = (__float_as_int(r) << 23) + (127 << 23);
    return p * __int_as_float(sb);
}
__device__ __forceinline__ void mma_f16(float c[4],
                                        uint32_t a0, uint32_t a1, uint32_t a2, uint32_t a3,
                                        uint32_t b0, uint32_t b1) {
    asm volatile(
        "mma.sync.aligned.m16n8k16.row.col.f32.f16.f16.f32 "
        "{%0,%1,%2,%3}, {%4,%5,%6,%7}, {%8,%9}, {%0,%1,%2,%3};"
        : "+f"(c[0]), "+f"(c[1]), "+f"(c[2]), "+f"(c[3])
        : "r"(a0), "r"(a1), "r"(a2), "r"(a3), "r"(b0), "r"(b1));
}
__device__ __forceinline__ void ldsm_x4(uint32_t& r0, uint32_t& r1, uint32_t& r2, uint32_t& r3,
                                        uint32_t addr) {
    asm volatile("ldmatrix.sync.aligned.m8n8.x4.shared.b16 {%0,%1,%2,%3}, [%4];"
                 : "=r"(r0), "=r"(r1), "=r"(r2), "=r"(r3) : "r"(addr));
}
__device__ __forceinline__ void ldsm_x4t(uint32_t& r0, uint32_t& r1, uint32_t& r2, uint32_t& r3,
                                         uint32_t addr) {
    asm volatile("ldmatrix.sync.aligned.m8n8.x4.trans.shared.b16 {%0,%1,%2,%3}, [%4];"
                 : "=r"(r0), "=r"(r1), "=r"(r2), "=r"(r3) : "r"(addr));
}
__device__ __forceinline__ uint32_t ldsmA_off(int lane, int stride_bytes) {
    return (uint32_t)((lane & 15) * stride_bytes + (((lane >> 4) & 1) << 4));
}
__device__ __forceinline__ uint32_t ldsmB_off(int lane, int stride_bytes) {
    int row = (lane & 7) + ((lane & 16) >> 1);
    return (uint32_t)(row * stride_bytes + (((lane >> 3) & 1) << 4));
}
__device__ __forceinline__ __half2 fh2(float x, float y) { return __floats2half2_rn(x, y); }

#define CP16(s, g)  asm volatile("cp.async.cg.shared.global [%0], [%1], 16;" :: "r"(s), "l"(g))
#define CPCOMMIT()  asm volatile("cp.async.commit_group;")
#define CPWAIT(n)   asm volatile("cp.async.wait_group " #n ";")

// ---------------------------------------------------------------------------
// Fused fp32 -> fp16 convert (one launch, region dispatch)
// ---------------------------------------------------------------------------
__global__ __launch_bounds__(256) void k_cvt_all(
    const float* __restrict__ x,  const float* __restrict__ wq,
    const float* __restrict__ wk, const float* __restrict__ wv,
    const float* __restrict__ wo)
{
    const int b = blockIdx.x;
    const float* s; __half* d; int base;
    if (b < 2048)      { s = x;  d = g_xh;  base = b; }
    else if (b < 4096) { s = wq; d = g_wqh; base = b - 2048; }
    else if (b < 4608) { s = wk; d = g_wkh; base = b - 4096; }
    else if (b < 5120) { s = wv; d = g_wvh; base = b - 4608; }
    else               { s = wo; d = g_woh; base = b - 5120; }
    const int i = (base * 256 + threadIdx.x) * 8;
    float4 a = *(const float4*)(s + i);
    float4 c = *(const float4*)(s + i + 4);
    __half2 h0 = fh2(a.x, a.y), h1 = fh2(a.z, a.w);
    __half2 h2 = fh2(c.x, c.y), h3 = fh2(c.z, c.w);
    uint4 u;
    u.x = *(uint32_t*)&h0; u.y = *(uint32_t*)&h1;
    u.z = *(uint32_t*)&h2; u.w = *(uint32_t*)&h3;
    *(uint4*)(d + i) = u;
}

// ---------------------------------------------------------------------------
// TN GEMM (fp16 in, cp.async 6-stage ring, TWO 16-K chunks per barrier):
// C = A[M,K]*B[N,K]^T.  Compute body identical to the proven 16-K version;
// only the loop skeleton changed (one __syncthreads per 2 chunks).
// ---------------------------------------------------------------------------
#define GSTR  24
#define GSTRB (GSTR * 2)
#define NSTG6 6
#define STGB  (128 * GSTRB)                   // 6144 B per stage per operand
#define GEMM_SMEM (2 * NSTG6 * STGB)          // 73728 B

template <bool HALF_OUT>
__device__ __forceinline__ void gemm_tn_f16(
    const __half* __restrict__ A, int lda,
    const __half* __restrict__ B, int ldb,
    void* __restrict__ Cv, int ldc,
    int K, int bm, int bn)
{
    extern __shared__ char gsm[];
    const int tid  = threadIdx.x;
    const int lane = tid & 31;
    const int w    = tid >> 5;
    const int wm   = w >> 1;
    const int wn   = w & 1;

    float acc[2][8][4];
#pragma unroll
    for (int mt = 0; mt < 2; mt++)
#pragma unroll
        for (int nt = 0; nt < 8; nt++)
#pragma unroll
            for (int i = 0; i < 4; i++) acc[mt][nt][i] = 0.f;

    const int lrow = tid >> 1;
    const int lch  = (tid & 1) << 3;
    const __half* Ag = A + (size_t)(bm + lrow) * lda + lch;
    const __half* Bg = B + (size_t)(bn + lrow) * ldb + lch;

    const uint32_t asb = (uint32_t)__cvta_generic_to_shared(gsm);
    const uint32_t bsb = asb + NSTG6 * STGB;
    const uint32_t ldo = (uint32_t)(lrow * GSTRB + lch * 2);
    const uint32_t aoff = ldsmA_off(lane, GSTRB) + (uint32_t)(wm * 32) * GSTRB;
    const uint32_t boff = ldsmB_off(lane, GSTRB) + (uint32_t)(wn * 64) * GSTRB;

    const int nch = K >> 4;                    // 128 (even)

    // prologue: chunks 0..3 -> stages 0..3 (one commit group per chunk)
#pragma unroll
    for (int s = 0; s < 4; s++) {
        CP16(asb + s * STGB + ldo, Ag + s * 16);
        CP16(bsb + s * STGB + ldo, Bg + s * 16);
        CPCOMMIT();
    }

    for (int c = 0; c < nch; c += 2) {
        CPWAIT(2);                             // chunks c, c+1 resident
        __syncthreads();                       // all warps done with pair c-2

        // prefetch chunks c+4, c+5 into stages (c+4)%6, (c+5)%6
        if (c + 4 < nch) {
            const uint32_t st = (uint32_t)((c + 4) % NSTG6) * STGB;
            CP16(asb + st + ldo, Ag + (c + 4) * 16);
            CP16(bsb + st + ldo, Bg + (c + 4) * 16);
        }
        CPCOMMIT();
        if (c + 5 < nch) {
            const uint32_t st = (uint32_t)((c + 5) % NSTG6) * STGB;
            CP16(asb + st + ldo, Ag + (c + 5) * 16);
            CP16(bsb + st + ldo, Bg + (c + 5) * 16);
        }
        CPCOMMIT();

        // compute chunks c and c+1
#pragma unroll
        for (int half = 0; half < 2; half++) {
            const uint32_t st = (uint32_t)((c + half) % NSTG6) * STGB;
            const uint32_t ab = asb + st + aoff;
            const uint32_t bb = bsb + st + boff;
            uint32_t a[2][4];
            ldsm_x4(a[0][0], a[0][1], a[0][2], a[0][3], ab);
            ldsm_x4(a[1][0], a[1][1], a[1][2], a[1][3], ab + 16 * GSTRB);
#pragma unroll
            for (int pr = 0; pr < 4; pr++) {
                uint32_t b0, b1, b2, b3;
                ldsm_x4(b0, b1, b2, b3, bb + (uint32_t)pr * 16 * GSTRB);
                mma_f16(acc[0][2 * pr],     a[0][0], a[0][1], a[0][2], a[0][3], b0, b1);
                mma_f16(acc[1][2 * pr],     a[1][0], a[1][1], a[1][2], a[1][3], b0, b1);
                mma_f16(acc[0][2 * pr + 1], a[0][0], a[0][1], a[0][2], a[0][3], b2, b3);
                mma_f16(acc[1][2 * pr + 1], a[1][0], a[1][1], a[1][2], a[1][3], b2, b3);
            }
        }
    }

    const int ar = lane >> 2;
    const int ak = lane & 3;
#pragma unroll
    for (int mt = 0; mt < 2; mt++) {
        const int r0 = bm + wm * 32 + mt * 16 + ar;
#pragma unroll
        for (int nt = 0; nt < 8; nt++) {
            const int cidx = bn + wn * 64 + nt * 8 + 2 * ak;
            if (HALF_OUT) {
                __half* C = (__half*)Cv;
                *(__half2*)(C + (size_t)r0 * ldc + cidx)       = fh2(acc[mt][nt][0], acc[mt][nt][1]);
                *(__half2*)(C + (size_t)(r0 + 8) * ldc + cidx) = fh2(acc[mt][nt][2], acc[mt][nt][3]);
            } else {
                float* C = (float*)Cv;
                *(float2*)(C + (size_t)r0 * ldc + cidx)       = make_float2(acc[mt][nt][0], acc[mt][nt][1]);
                *(float2*)(C + (size_t)(r0 + 8) * ldc + cidx) = make_float2(acc[mt][nt][2], acc[mt][nt][3]);
            }
        }
    }
}

__global__ __launch_bounds__(256, 2) void k_gemm_qkv(
    const __half* __restrict__ x,
    const __half* __restrict__ wq, const __half* __restrict__ wk,
    const __half* __restrict__ wv,
    __half* __restrict__ q, __half* __restrict__ k, __half* __restrict__ v)
{
    const int bnx = blockIdx.x * 128;
    const __half* B; __half* C; int ldc; int bn;
    if (bnx < HID)            { B = wq; C = q; ldc = HID; bn = bnx; }
    else if (bnx < HID + KVW) { B = wk; C = k; ldc = KVW; bn = bnx - HID; }
    else                      { B = wv; C = v; ldc = KVW; bn = bnx - HID - KVW; }
    gemm_tn_f16<true>(x, HID, B, HID, C, ldc, HID, blockIdx.y * 128, bn);
}

__global__ __launch_bounds__(256, 2) void k_gemm_o(
    const __half* __restrict__ A, const __half* __restrict__ B,
    float* __restrict__ C)
{
    gemm_tn_f16<false>(A, HID, B, HID, C, HID, HID, blockIdx.y * 128, blockIdx.x * 128);
}

// ---------------------------------------------------------------------------
// Fused flash attention (unchanged from R14): fp16 mma, BK=128, 512 CTAs
// longest-first, pipelined K/V prefetch, fixed-bias softmax.
// ---------------------------------------------------------------------------
#define FSTR  136
#define FSTRB (FSTR * 2)
#define QS_OFF   0
#define KS_OFF   (64 * FSTRB)
#define VS_OFF   (KS_OFF + 128 * FSTRB)
#define PS_OFF   (VS_OFF + 128 * FSTRB)
#define RSM_OFF  (PS_OFF + 64 * FSTRB)
#define FLASH_SMEM (RSM_OFF + 4 * 64 * 4)        // 105472

__global__ __launch_bounds__(256, 2) void k_flash(
    const __half* __restrict__ Qg, const __half* __restrict__ Kg,
    const __half* __restrict__ Vg, __half* __restrict__ Ctx,
    const float* __restrict__ sin_t, const float* __restrict__ cos_t,
    const float* __restrict__ qnw)
{
    extern __shared__ char smem[];
    __half (*Qs)[FSTR]  = (__half(*)[FSTR])(smem + QS_OFF);
    __half (*Ps)[FSTR]  = (__half(*)[FSTR])(smem + PS_OFF);
    float (*redsum)[64] = (float(*)[64])(smem + RSM_OFF);

    const int bid = blockIdx.x;
    const int h   = bid & 15;
    const int qi  = 31 - (bid >> 4);
    const int kvh = h >> 2;

    const int tid  = threadIdx.x;
    const int lane = tid & 31;
    const int w    = tid >> 5;
    const int wm   = w >> 2;
    const int wn   = w & 3;
    const int ar   = lane >> 2;
    const int ak   = lane & 3;
    const float C  = (float)(0.08838834764831843 * 1.4426950408889634);
    const float BIAS = 8.0f;

    const uint32_t qsb = (uint32_t)__cvta_generic_to_shared(&Qs[0][0]);
    const uint32_t ksb = (uint32_t)__cvta_generic_to_shared(smem + KS_OFF);
    const uint32_t vsb = (uint32_t)__cvta_generic_to_shared(smem + VS_OFF);
    const uint32_t psb = (uint32_t)__cvta_generic_to_shared(smem + PS_OFF);
    const uint32_t aoff = ldsmA_off(lane, FSTRB) + (uint32_t)(wm * 32) * FSTRB;
    const uint32_t boff = ldsmB_off(lane, FSTRB) + (uint32_t)(wn * 32) * FSTRB;
    const uint32_t voff = (uint32_t)(((lane & 7) + ((lane >> 3) & 1) * 8) * FSTRB
                                     + (((lane >> 4) & 1) * 8 + wn * 32) * 2);

    // Q tile [64 x 128]: fp16 q -> fp32 RMSNorm + RoPE -> fp16 smem
    {
        const int r  = tid >> 2;
        const int c0 = (tid & 3) << 2;
        const int s  = qi * 64 + r;
        const __half* qp = Qg + (size_t)s * HID + h * DHEAD;
        float4 qa[8];
        float ss = 0.f;
#pragma unroll
        for (int i = 0; i < 8; i++) {
            const __half2* ph = (const __half2*)(qp + c0 + 16 * i);
            float2 f01 = __half22float2(ph[0]);
            float2 f23 = __half22float2(ph[1]);
            qa[i] = make_float4(f01.x, f01.y, f23.x, f23.y);
            ss += qa[i].x * qa[i].x + qa[i].y * qa[i].y + qa[i].z * qa[i].z + qa[i].w * qa[i].w;
        }
        ss += __shfl_xor_sync(0xffffffffu, ss, 1);
        ss += __shfl_xor_sync(0xffffffffu, ss, 2);
        const float inv = rsqrtf(ss * (1.0f / 128.0f) + 1.1920928955078125e-07f);
        float4 xn[8];
#pragma unroll
        for (int i = 0; i < 8; i++) {
            float4 wv4 = *(const float4*)(qnw + c0 + 16 * i);
            xn[i] = make_float4(qa[i].x * inv * wv4.x, qa[i].y * inv * wv4.y,
                                qa[i].z * inv * wv4.z, qa[i].w * inv * wv4.w);
        }
        const float* sp = sin_t + (size_t)s * DHEAD;
        const float* cp = cos_t + (size_t)s * DHEAD;
#pragma unroll
        for (int i = 0; i < 8; i++) {
            const int c = c0 + 16 * i;
            float4 s4 = *(const float4*)(sp + c);
            float4 c4 = *(const float4*)(cp + c);
            float4 rot = (i < 4)
                ? make_float4(-xn[i + 4].x, -xn[i + 4].y, -xn[i + 4].z, -xn[i + 4].w)
                : xn[i - 4];
            *(__half2*)&Qs[r][c]     = fh2(c4.x * xn[i].x + s4.x * rot.x,
                                           c4.y * xn[i].y + s4.y * rot.y);
            *(__half2*)&Qs[r][c + 2] = fh2(c4.z * xn[i].z + s4.z * rot.z,
                                           c4.w * xn[i].w + s4.w * rot.w);
        }
    }

    float o[2][4][4];
    float l_st[2][2];
#pragma unroll
    for (int mt = 0; mt < 2; mt++) {
#pragma unroll
        for (int nt = 0; nt < 4; nt++)
#pragma unroll
            for (int c = 0; c < 4; c++) o[mt][nt][c] = 0.f;
        l_st[mt][0] = l_st[mt][1] = 0.f;
    }

    const int nj = (qi >> 1) + 1;
    const __half* Kbase = Kg + kvh * DHEAD;
    const __half* Vbase = Vg + kvh * DHEAD;
    const int lr8 = tid >> 4;
    const int lc8 = (tid & 15) << 3;

    {
#pragma unroll
        for (int it = 0; it < 8; it++) {
            const int r = lr8 + 16 * it;
            CP16(ksb + r * FSTRB + lc8 * 2, Kbase + (size_t)r * KVW + lc8);
        }
        CPCOMMIT();
#pragma unroll
        for (int it = 0; it < 8; it++) {
            const int r = lr8 + 16 * it;
            CP16(vsb + r * FSTRB + lc8 * 2, Vbase + (size_t)r * KVW + lc8);
        }
        CPCOMMIT();
    }

    for (int j = 0; j < nj; j++) {
        CPWAIT(1);
        __syncthreads();

        float s[2][4][4];
#pragma unroll
        for (int mt = 0; mt < 2; mt++)
#pragma unroll
            for (int nt = 0; nt < 4; nt++)
#pragma unroll
                for (int c = 0; c < 4; c++) s[mt][nt][c] = 0.f;
#pragma unroll
        for (int ks = 0; ks < 128; ks += 16) {
            uint32_t a[2][4];
            ldsm_x4(a[0][0], a[0][1], a[0][2], a[0][3], qsb + aoff + ks * 2);
            ldsm_x4(a[1][0], a[1][1], a[1][2], a[1][3], qsb + aoff + 16 * FSTRB + ks * 2);
#pragma unroll
            for (int pr = 0; pr < 2; pr++) {
                uint32_t b0, b1, b2, b3;
                ldsm_x4(b0, b1, b2, b3, ksb + boff + (uint32_t)pr * 16 * FSTRB + ks * 2);
                mma_f16(s[0][2 * pr],     a[0][0], a[0][1], a[0][2], a[0][3], b0, b1);
                mma_f16(s[1][2 * pr],     a[1][0], a[1][1], a[1][2], a[1][3], b0, b1);
                mma_f16(s[0][2 * pr + 1], a[0][0], a[0][1], a[0][2], a[0][3], b2, b3);
                mma_f16(s[1][2 * pr + 1], a[1][0], a[1][1], a[1][2], a[1][3], b2, b3);
            }
        }
        __syncthreads();

        if (j + 1 < nj) {
            const __half* kb = Kbase + (size_t)((j + 1) * 128) * KVW;
#pragma unroll
            for (int it = 0; it < 8; it++) {
                const int r = lr8 + 16 * it;
                CP16(ksb + r * FSTRB + lc8 * 2, kb + (size_t)r * KVW + lc8);
            }
        }
        CPCOMMIT();

        if (j == nj - 1) {
            const int col0 = j * 128;
            const int row0 = qi * 64;
#pragma unroll
            for (int mt = 0; mt < 2; mt++)
#pragma unroll
                for (int nt = 0; nt < 4; nt++) {
                    const int colb = col0 + wn * 32 + nt * 8 + 2 * ak;
#pragma unroll
                    for (int cc = 0; cc < 4; cc++) {
                        const int row_g = row0 + wm * 32 + mt * 16 + ar + (cc >> 1) * 8;
                        const int col_g = colb + (cc & 1);
                        if (col_g > row_g) s[mt][nt][cc] = -1e30f;
                    }
                }
        }

#pragma unroll
        for (int mt = 0; mt < 2; mt++) {
#pragma unroll
            for (int nt = 0; nt < 4; nt++) {
                const int colb = wn * 32 + nt * 8 + 2 * ak;
                float p0 = exp2poly(fmaf(s[mt][nt][0], C, -BIAS));
                float p1 = exp2poly(fmaf(s[mt][nt][1], C, -BIAS));
                float p2, p3;
                if (nt < 2) {
                    p2 = exp2poly(fmaf(s[mt][nt][2], C, -BIAS));
                    p3 = (nt == 0) ? exp2poly(fmaf(s[mt][nt][3], C, -BIAS))
                                   : ex2(fmaf(s[mt][nt][3], C, -BIAS));
                } else {
                    p2 = ex2(fmaf(s[mt][nt][2], C, -BIAS));
                    p3 = ex2(fmaf(s[mt][nt][3], C, -BIAS));
                }
                l_st[mt][0] += p0 + p1;
                l_st[mt][1] += p2 + p3;
                const int r0 = wm * 32 + mt * 16 + ar;
                *(__half2*)&Ps[r0][colb]     = fh2(p0, p1);
                *(__half2*)&Ps[r0 + 8][colb] = fh2(p2, p3);
            }
        }
        CPWAIT(1);
        __syncthreads();

#pragma unroll
        for (int ks = 0; ks < 128; ks += 16) {
            uint32_t a[2][4];
            ldsm_x4(a[0][0], a[0][1], a[0][2], a[0][3], psb + aoff + ks * 2);
            ldsm_x4(a[1][0], a[1][1], a[1][2], a[1][3], psb + aoff + 16 * FSTRB + ks * 2);
#pragma unroll
            for (int half_n = 0; half_n < 2; half_n++) {
                uint32_t b0, b1, b2, b3;
                ldsm_x4t(b0, b1, b2, b3, vsb + voff + (uint32_t)ks * FSTRB + half_n * 32);
                mma_f16(o[0][2 * half_n],     a[0][0], a[0][1], a[0][2], a[0][3], b0, b1);
                mma_f16(o[1][2 * half_n],     a[1][0], a[1][1], a[1][2], a[1][3], b0, b1);
                mma_f16(o[0][2 * half_n + 1], a[0][0], a[0][1], a[0][2], a[0][3], b2, b3);
                mma_f16(o[1][2 * half_n + 1], a[1][0], a[1][1], a[1][2], a[1][3], b2, b3);
            }
        }
        __syncthreads();

        if (j + 1 < nj) {
            const __half* vb = Vbase + (size_t)((j + 1) * 128) * KVW;
#pragma unroll
            for (int it = 0; it < 8; it++) {
                const int r = lr8 + 16 * it;
                CP16(vsb + r * FSTRB + lc8 * 2, vb + (size_t)r * KVW + lc8);
            }
        }
        CPCOMMIT();
    }

#pragma unroll
    for (int mt = 0; mt < 2; mt++) {
        l_st[mt][0] += __shfl_xor_sync(0xffffffffu, l_st[mt][0], 1);
        l_st[mt][0] += __shfl_xor_sync(0xffffffffu, l_st[mt][0], 2);
        l_st[mt][1] += __shfl_xor_sync(0xffffffffu, l_st[mt][1], 1);
        l_st[mt][1] += __shfl_xor_sync(0xffffffffu, l_st[mt][1], 2);
        if (ak == 0) {
            redsum[wn][wm * 32 + mt * 16 + ar]     = l_st[mt][0];
            redsum[wn][wm * 32 + mt * 16 + ar + 8] = l_st[mt][1];
        }
    }
    __syncthreads();

#pragma unroll
    for (int mt = 0; mt < 2; mt++) {
        const int r0 = wm * 32 + mt * 16 + ar;
        const float l0 = (redsum[0][r0] + redsum[1][r0]) + (redsum[2][r0] + redsum[3][r0]);
        const float l1 = (redsum[0][r0 + 8] + redsum[1][r0 + 8]) + (redsum[2][r0 + 8] + redsum[3][r0 + 8]);
        const float i0 = 1.f / l0;
        const float i1 = 1.f / l1;
        __half* c0p = Ctx + (size_t)(qi * 64 + r0) * HID + h * DHEAD;
        __half* c1p = c0p + 8 * HID;
#pragma unroll
        for (int nt = 0; nt < 4; nt++) {
            const int cb = wn * 32 + nt * 8 + 2 * ak;
            *(__half2*)(c0p + cb) = fh2(o[mt][nt][0] * i0, o[mt][nt][1] * i0);
            *(__half2*)(c1p + cb) = fh2(o[mt][nt][2] * i1, o[mt][nt][3] * i1);
        }
    }
}

// ---------------------------------------------------------------------------
// Per-(s,kvhead) RMSNorm + RoPE for K, in place on fp16.
// ---------------------------------------------------------------------------
__global__ __launch_bounds__(128) void k_normrope_h(
    __half* __restrict__ X, int rowstride,
    const float* __restrict__ sin_t, const float* __restrict__ cos_t,
    const float* __restrict__ w)
{
    const int s = blockIdx.x;
    const int h = blockIdx.y;
    const int d = threadIdx.x;
    __half* row = X + (size_t)s * rowstride + h * DHEAD;
    float v = __half2float(row[d]);
    float ss = v * v;
#pragma unroll
    for (int o = 16; o > 0; o >>= 1) ss += __shfl_xor_sync(0xffffffffu, ss, o);
    __shared__ float wsum[4];
    if ((d & 31) == 0) wsum[d >> 5] = ss;
    __syncthreads();
    float tot = wsum[0] + wsum[1] + wsum[2] + wsum[3];
    float inv = rsqrtf(tot * (1.0f / 128.0f) + 1.1920928955078125e-07f);
    __shared__ float xn[128];
    float xv = v * inv * w[d];
    xn[d] = xv;
    __syncthreads();
    float rot = (d < 64) ? -xn[d + 64] : xn[d - 64];
    row[d] = __float2half(cos_t[s * DHEAD + d] * xv + sin_t[s * DHEAD + d] * rot);
}

// ---------------------------------------------------------------------------
// Launch
// ---------------------------------------------------------------------------
extern "C" void kernel_launch(void* const* d_in, const int* in_sizes, int n_in,
                              void* d_out, int out_size)
{
    (void)in_sizes; (void)n_in; (void)out_size;
    const float* x     = (const float*)d_in[0];
    const float* sin_t = (const float*)d_in[1];
    const float* cos_t = (const float*)d_in[2];
    const float* wq    = (const float*)d_in[4];
    const float* wk    = (const float*)d_in[5];
    const float* wv    = (const float*)d_in[6];
    const float* wo    = (const float*)d_in[7];
    const float* qnw   = (const float*)d_in[8];
    const float* knw   = (const float*)d_in[9];
    float* out = (float*)d_out;

    __half *xh, *wqh, *wkh, *wvh, *woh, *qh, *kh, *vh, *ctxh;
    cudaGetSymbolAddress((void**)&xh,   g_xh);
    cudaGetSymbolAddress((void**)&wqh,  g_wqh);
    cudaGetSymbolAddress((void**)&wkh,  g_wkh);
    cudaGetSymbolAddress((void**)&wvh,  g_wvh);
    cudaGetSymbolAddress((void**)&woh,  g_woh);
    cudaGetSymbolAddress((void**)&qh,   g_qh);
    cudaGetSymbolAddress((void**)&kh,   g_kh);
    cudaGetSymbolAddress((void**)&vh,   g_vh);
    cudaGetSymbolAddress((void**)&ctxh, g_ctxh);

    cudaFuncSetAttribute(k_flash,    cudaFuncAttributeMaxDynamicSharedMemorySize, FLASH_SMEM);
    cudaFuncSetAttribute(k_gemm_qkv, cudaFuncAttributeMaxDynamicSharedMemorySize, GEMM_SMEM);
    cudaFuncSetAttribute(k_gemm_o,   cudaFuncAttributeMaxDynamicSharedMemorySize, GEMM_SMEM);

    // One fused fp32 -> fp16 conversion launch
    k_cvt_all<<<7168, 256>>>(x, wq, wk, wv, wo);

    // Fused QKV projection (fp16 in/out, 6-stage ring, 1 barrier per 2 chunks)
    k_gemm_qkv<<<dim3((HID + 2 * KVW) / 128, SEQ / 128), 256, GEMM_SMEM>>>(
        xh, wqh, wkh, wvh, qh, kh, vh);

    // RMSNorm + RoPE for K
    k_normrope_h<<<dim3(SEQ, NKVH), 128>>>(kh, KVW, sin_t, cos_t, knw);

    // Fused flash attention
    k_flash<<<512, 256, FLASH_SMEM>>>(qh, kh, vh, ctxh, sin_t, cos_t, qnw);

    // Output projection (fp16 in, fp32 out)
    k_gemm_o<<<dim3(HID / 128, SEQ / 128), 256, GEMM_SMEM>>>(ctxh, woh, out);
}

// round 16
// speedup vs baseline: 1.1912x; 1.1912x over previous
#include <cuda_runtime.h>
#include <cuda_fp16.h>
#include <math.h>
#include <stddef.h>
#include <stdint.h>

// Problem constants (B=1)
#define SEQ   2048
#define HID   2048
#define NHEADS 16
#define NKVH   4
#define DHEAD  128
#define KVW   (NKVH * DHEAD)      // 512
#define GQA_REP (NHEADS / NKVH)   // 4

// fp16 scratch
__device__ __half g_xh [SEQ * HID];
__device__ __half g_wqh[HID * HID];
__device__ __half g_wkh[KVW * HID];
__device__ __half g_wvh[KVW * HID];
__device__ __half g_woh[HID * HID];
__device__ __half g_qh [SEQ * HID];
__device__ __half g_kh [SEQ * KVW];
__device__ __half g_vh [SEQ * KVW];
__device__ __half g_ctxh[SEQ * HID];

// ---------------------------------------------------------------------------
// helpers
// ---------------------------------------------------------------------------
__device__ __forceinline__ float ex2(float x) {
    float y;
    asm("ex2.approx.ftz.f32 %0, %1;" : "=f"(y) : "f"(x));
    return y;
}
__device__ __forceinline__ float exp2poly(float x) {
    const float MAGIC = 12582912.f;
    float t = fmaxf(x, -126.f);
    float r = t + MAGIC;
    float n = r - MAGIC;
    float f = t - n;
    float p = 1.3333558146e-3f;
    p = fmaf(p, f, 9.6181291076e-3f);
    p = fmaf(p, f, 5.5504108664e-2f);
    p = fmaf(p, f, 2.4022650696e-1f);
    p = fmaf(p, f, 6.9314718056e-1f);
    p = fmaf(p, f, 1.0f);
    int sb = (__float_as_int(r) << 23) + (127 << 23);
    return p * __int_as_float(sb);
}
__device__ __forceinline__ void mma_f16(float c[4],
                                        uint32_t a0, uint32_t a1, uint32_t a2, uint32_t a3,
                                        uint32_t b0, uint32_t b1) {
    asm volatile(
        "mma.sync.aligned.m16n8k16.row.col.f32.f16.f16.f32 "
        "{%0,%1,%2,%3}, {%4,%5,%6,%7}, {%8,%9}, {%0,%1,%2,%3};"
        : "+f"(c[0]), "+f"(c[1]), "+f"(c[2]), "+f"(c[3])
        : "r"(a0), "r"(a1), "r"(a2), "r"(a3), "r"(b0), "r"(b1));
}
__device__ __forceinline__ void ldsm_x4(uint32_t& r0, uint32_t& r1, uint32_t& r2, uint32_t& r3,
                                        uint32_t addr) {
    asm volatile("ldmatrix.sync.aligned.m8n8.x4.shared.b16 {%0,%1,%2,%3}, [%4];"
                 : "=r"(r0), "=r"(r1), "=r"(r2), "=r"(r3) : "r"(addr));
}
__device__ __forceinline__ void ldsm_x4t(uint32_t& r0, uint32_t& r1, uint32_t& r2, uint32_t& r3,
                                         uint32_t addr) {
    asm volatile("ldmatrix.sync.aligned.m8n8.x4.trans.shared.b16 {%0,%1,%2,%3}, [%4];"
                 : "=r"(r0), "=r"(r1), "=r"(r2), "=r"(r3) : "r"(addr));
}
__device__ __forceinline__ uint32_t ldsmA_off(int lane, int stride_bytes) {
    return (uint32_t)((lane & 15) * stride_bytes + (((lane >> 4) & 1) << 4));
}
__device__ __forceinline__ uint32_t ldsmB_off(int lane, int stride_bytes) {
    int row = (lane & 7) + ((lane & 16) >> 1);
    return (uint32_t)(row * stride_bytes + (((lane >> 3) & 1) << 4));
}
__device__ __forceinline__ __half2 fh2(float x, float y) { return __floats2half2_rn(x, y); }

#define CP16(s, g)  asm volatile("cp.async.cg.shared.global [%0], [%1], 16;" :: "r"(s), "l"(g))
#define CPCOMMIT()  asm volatile("cp.async.commit_group;")
#define CPWAIT(n)   asm volatile("cp.async.wait_group " #n ";")

// ---------------------------------------------------------------------------
// Fused fp32 -> fp16 convert, 16 elems/thread (one launch, region dispatch)
// blocks (4096 elems each): x 1024 | wq 1024 | wk 256 | wv 256 | wo 1024
// ---------------------------------------------------------------------------
__global__ __launch_bounds__(256) void k_cvt_all(
    const float* __restrict__ x,  const float* __restrict__ wq,
    const float* __restrict__ wk, const float* __restrict__ wv,
    const float* __restrict__ wo)
{
    const int b = blockIdx.x;
    const float* s; __half* d; int base;
    if (b < 1024)      { s = x;  d = g_xh;  base = b; }
    else if (b < 2048) { s = wq; d = g_wqh; base = b - 1024; }
    else if (b < 2304) { s = wk; d = g_wkh; base = b - 2048; }
    else if (b < 2560) { s = wv; d = g_wvh; base = b - 2304; }
    else               { s = wo; d = g_woh; base = b - 2560; }
    const int i = (base * 256 + threadIdx.x) * 16;
#pragma unroll
    for (int q = 0; q < 2; q++) {
        float4 a = *(const float4*)(s + i + q * 8);
        float4 c = *(const float4*)(s + i + q * 8 + 4);
        __half2 h0 = fh2(a.x, a.y), h1 = fh2(a.z, a.w);
        __half2 h2 = fh2(c.x, c.y), h3 = fh2(c.z, c.w);
        uint4 u;
        u.x = *(uint32_t*)&h0; u.y = *(uint32_t*)&h1;
        u.z = *(uint32_t*)&h2; u.w = *(uint32_t*)&h3;
        *(uint4*)(d + i + q * 8) = u;
    }
}

// ---------------------------------------------------------------------------
// TN GEMM (fp16 in via cp.async 4-stage pipeline): C = A[M,K]*B[N,K]^T
// (frozen: proven body from R9-R14)
// ---------------------------------------------------------------------------
#define GSTR  24
#define GSTRB (GSTR * 2)
#define NSTG  4
#define STGB  (128 * GSTRB)

template <bool HALF_OUT>
__device__ __forceinline__ void gemm_tn_f16(
    const __half* __restrict__ A, int lda,
    const __half* __restrict__ B, int ldb,
    void* __restrict__ Cv, int ldc,
    int K, int bm, int bn)
{
    __shared__ __half As[NSTG][128][GSTR];
    __shared__ __half Bs[NSTG][128][GSTR];
    const int tid  = threadIdx.x;
    const int lane = tid & 31;
    const int w    = tid >> 5;
    const int wm   = w >> 1;
    const int wn   = w & 1;

    float acc[2][8][4];
#pragma unroll
    for (int mt = 0; mt < 2; mt++)
#pragma unroll
        for (int nt = 0; nt < 8; nt++)
#pragma unroll
            for (int i = 0; i < 4; i++) acc[mt][nt][i] = 0.f;

    const int lrow = tid >> 1;
    const int lch  = (tid & 1) << 3;
    const __half* Ag = A + (size_t)(bm + lrow) * lda + lch;
    const __half* Bg = B + (size_t)(bn + lrow) * ldb + lch;
    const uint32_t sA = (uint32_t)__cvta_generic_to_shared(&As[0][0][0]) + lrow * GSTRB + lch * 2;
    const uint32_t sB = (uint32_t)__cvta_generic_to_shared(&Bs[0][0][0]) + lrow * GSTRB + lch * 2;

    const uint32_t asb = (uint32_t)__cvta_generic_to_shared(&As[0][0][0]);
    const uint32_t bsb = (uint32_t)__cvta_generic_to_shared(&Bs[0][0][0]);
    const uint32_t aoff = ldsmA_off(lane, GSTRB) + (uint32_t)(wm * 32) * GSTRB;
    const uint32_t boff = ldsmB_off(lane, GSTRB) + (uint32_t)(wn * 64) * GSTRB;

    const int nch = K >> 4;
#pragma unroll
    for (int s = 0; s < NSTG - 1; s++) {
        CP16(sA + s * STGB, Ag + s * 16);
        CP16(sB + s * STGB, Bg + s * 16);
        CPCOMMIT();
    }

    for (int i = 0; i < nch; i++) {
        CPWAIT(2);
        __syncthreads();
        const int nc = i + NSTG - 1;
        if (nc < nch) {
            const uint32_t stg = (uint32_t)(nc & (NSTG - 1)) * STGB;
            CP16(sA + stg, Ag + nc * 16);
            CP16(sB + stg, Bg + nc * 16);
        }
        CPCOMMIT();

        const uint32_t st = (uint32_t)(i & (NSTG - 1)) * STGB;
        const uint32_t ab = asb + st + aoff;
        const uint32_t bb = bsb + st + boff;
        uint32_t a[2][4];
        ldsm_x4(a[0][0], a[0][1], a[0][2], a[0][3], ab);
        ldsm_x4(a[1][0], a[1][1], a[1][2], a[1][3], ab + 16 * GSTRB);
#pragma unroll
        for (int pr = 0; pr < 4; pr++) {
            uint32_t b0, b1, b2, b3;
            ldsm_x4(b0, b1, b2, b3, bb + (uint32_t)pr * 16 * GSTRB);
            mma_f16(acc[0][2 * pr],     a[0][0], a[0][1], a[0][2], a[0][3], b0, b1);
            mma_f16(acc[1][2 * pr],     a[1][0], a[1][1], a[1][2], a[1][3], b0, b1);
            mma_f16(acc[0][2 * pr + 1], a[0][0], a[0][1], a[0][2], a[0][3], b2, b3);
            mma_f16(acc[1][2 * pr + 1], a[1][0], a[1][1], a[1][2], a[1][3], b2, b3);
        }
    }

    const int ar = lane >> 2;
    const int ak = lane & 3;
#pragma unroll
    for (int mt = 0; mt < 2; mt++) {
        const int r0 = bm + wm * 32 + mt * 16 + ar;
#pragma unroll
        for (int nt = 0; nt < 8; nt++) {
            const int cidx = bn + wn * 64 + nt * 8 + 2 * ak;
            if (HALF_OUT) {
                __half* C = (__half*)Cv;
                *(__half2*)(C + (size_t)r0 * ldc + cidx)       = fh2(acc[mt][nt][0], acc[mt][nt][1]);
                *(__half2*)(C + (size_t)(r0 + 8) * ldc + cidx) = fh2(acc[mt][nt][2], acc[mt][nt][3]);
            } else {
                float* C = (float*)Cv;
                *(float2*)(C + (size_t)r0 * ldc + cidx)       = make_float2(acc[mt][nt][0], acc[mt][nt][1]);
                *(float2*)(C + (size_t)(r0 + 8) * ldc + cidx) = make_float2(acc[mt][nt][2], acc[mt][nt][3]);
            }
        }
    }
}

__global__ __launch_bounds__(256, 2) void k_gemm_qkv(
    const __half* __restrict__ x,
    const __half* __restrict__ wq, const __half* __restrict__ wk,
    const __half* __restrict__ wv,
    __half* __restrict__ q, __half* __restrict__ k, __half* __restrict__ v)
{
    const int bnx = blockIdx.x * 128;
    const __half* B; __half* C; int ldc; int bn;
    if (bnx < HID)            { B = wq; C = q; ldc = HID; bn = bnx; }
    else if (bnx < HID + KVW) { B = wk; C = k; ldc = KVW; bn = bnx - HID; }
    else                      { B = wv; C = v; ldc = KVW; bn = bnx - HID - KVW; }
    gemm_tn_f16<true>(x, HID, B, HID, C, ldc, HID, blockIdx.y * 128, bn);
}

__global__ __launch_bounds__(256, 2) void k_gemm_o(
    const __half* __restrict__ A, const __half* __restrict__ B,
    float* __restrict__ C)
{
    gemm_tn_f16<false>(A, HID, B, HID, C, HID, HID, blockIdx.y * 128, blockIdx.x * 128);
}

// ---------------------------------------------------------------------------
// Fused flash attention (frozen: R14): fp16 mma, BK=128, 512 CTAs
// longest-first, pipelined K/V prefetch, fixed-bias softmax.
// ---------------------------------------------------------------------------
#define FSTR  136
#define FSTRB (FSTR * 2)
#define QS_OFF   0
#define KS_OFF   (64 * FSTRB)
#define VS_OFF   (KS_OFF + 128 * FSTRB)
#define PS_OFF   (VS_OFF + 128 * FSTRB)
#define RSM_OFF  (PS_OFF + 64 * FSTRB)
#define FLASH_SMEM (RSM_OFF + 4 * 64 * 4)        // 105472

__global__ __launch_bounds__(256, 2) void k_flash(
    const __half* __restrict__ Qg, const __half* __restrict__ Kg,
    const __half* __restrict__ Vg, __half* __restrict__ Ctx,
    const float* __restrict__ sin_t, const float* __restrict__ cos_t,
    const float* __restrict__ qnw)
{
    extern __shared__ char smem[];
    __half (*Qs)[FSTR]  = (__half(*)[FSTR])(smem + QS_OFF);
    __half (*Ps)[FSTR]  = (__half(*)[FSTR])(smem + PS_OFF);
    float (*redsum)[64] = (float(*)[64])(smem + RSM_OFF);

    const int bid = blockIdx.x;
    const int h   = bid & 15;
    const int qi  = 31 - (bid >> 4);
    const int kvh = h >> 2;

    const int tid  = threadIdx.x;
    const int lane = tid & 31;
    const int w    = tid >> 5;
    const int wm   = w >> 2;
    const int wn   = w & 3;
    const int ar   = lane >> 2;
    const int ak   = lane & 3;
    const float C  = (float)(0.08838834764831843 * 1.4426950408889634);
    const float BIAS = 8.0f;

    const uint32_t qsb = (uint32_t)__cvta_generic_to_shared(&Qs[0][0]);
    const uint32_t ksb = (uint32_t)__cvta_generic_to_shared(smem + KS_OFF);
    const uint32_t vsb = (uint32_t)__cvta_generic_to_shared(smem + VS_OFF);
    const uint32_t psb = (uint32_t)__cvta_generic_to_shared(smem + PS_OFF);
    const uint32_t aoff = ldsmA_off(lane, FSTRB) + (uint32_t)(wm * 32) * FSTRB;
    const uint32_t boff = ldsmB_off(lane, FSTRB) + (uint32_t)(wn * 32) * FSTRB;
    const uint32_t voff = (uint32_t)(((lane & 7) + ((lane >> 3) & 1) * 8) * FSTRB
                                     + (((lane >> 4) & 1) * 8 + wn * 32) * 2);

    // Q tile [64 x 128]: fp16 q -> fp32 RMSNorm + RoPE -> fp16 smem
    {
        const int r  = tid >> 2;
        const int c0 = (tid & 3) << 2;
        const int s  = qi * 64 + r;
        const __half* qp = Qg + (size_t)s * HID + h * DHEAD;
        float4 qa[8];
        float ss = 0.f;
#pragma unroll
        for (int i = 0; i < 8; i++) {
            const __half2* ph = (const __half2*)(qp + c0 + 16 * i);
            float2 f01 = __half22float2(ph[0]);
            float2 f23 = __half22float2(ph[1]);
            qa[i] = make_float4(f01.x, f01.y, f23.x, f23.y);
            ss += qa[i].x * qa[i].x + qa[i].y * qa[i].y + qa[i].z * qa[i].z + qa[i].w * qa[i].w;
        }
        ss += __shfl_xor_sync(0xffffffffu, ss, 1);
        ss += __shfl_xor_sync(0xffffffffu, ss, 2);
        const float inv = rsqrtf(ss * (1.0f / 128.0f) + 1.1920928955078125e-07f);
        float4 xn[8];
#pragma unroll
        for (int i = 0; i < 8; i++) {
            float4 wv4 = *(const float4*)(qnw + c0 + 16 * i);
            xn[i] = make_float4(qa[i].x * inv * wv4.x, qa[i].y * inv * wv4.y,
                                qa[i].z * inv * wv4.z, qa[i].w * inv * wv4.w);
        }
        const float* sp = sin_t + (size_t)s * DHEAD;
        const float* cp = cos_t + (size_t)s * DHEAD;
#pragma unroll
        for (int i = 0; i < 8; i++) {
            const int c = c0 + 16 * i;
            float4 s4 = *(const float4*)(sp + c);
            float4 c4 = *(const float4*)(cp + c);
            float4 rot = (i < 4)
                ? make_float4(-xn[i + 4].x, -xn[i + 4].y, -xn[i + 4].z, -xn[i + 4].w)
                : xn[i - 4];
            *(__half2*)&Qs[r][c]     = fh2(c4.x * xn[i].x + s4.x * rot.x,
                                           c4.y * xn[i].y + s4.y * rot.y);
            *(__half2*)&Qs[r][c + 2] = fh2(c4.z * xn[i].z + s4.z * rot.z,
                                           c4.w * xn[i].w + s4.w * rot.w);
        }
    }

    float o[2][4][4];
    float l_st[2][2];
#pragma unroll
    for (int mt = 0; mt < 2; mt++) {
#pragma unroll
        for (int nt = 0; nt < 4; nt++)
#pragma unroll
            for (int c = 0; c < 4; c++) o[mt][nt][c] = 0.f;
        l_st[mt][0] = l_st[mt][1] = 0.f;
    }

    const int nj = (qi >> 1) + 1;
    const __half* Kbase = Kg + kvh * DHEAD;
    const __half* Vbase = Vg + kvh * DHEAD;
    const int lr8 = tid >> 4;
    const int lc8 = (tid & 15) << 3;

    {
#pragma unroll
        for (int it = 0; it < 8; it++) {
            const int r = lr8 + 16 * it;
            CP16(ksb + r * FSTRB + lc8 * 2, Kbase + (size_t)r * KVW + lc8);
        }
        CPCOMMIT();
#pragma unroll
        for (int it = 0; it < 8; it++) {
            const int r = lr8 + 16 * it;
            CP16(vsb + r * FSTRB + lc8 * 2, Vbase + (size_t)r * KVW + lc8);
        }
        CPCOMMIT();
    }

    for (int j = 0; j < nj; j++) {
        CPWAIT(1);
        __syncthreads();

        float s[2][4][4];
#pragma unroll
        for (int mt = 0; mt < 2; mt++)
#pragma unroll
            for (int nt = 0; nt < 4; nt++)
#pragma unroll
                for (int c = 0; c < 4; c++) s[mt][nt][c] = 0.f;
#pragma unroll
        for (int ks = 0; ks < 128; ks += 16) {
            uint32_t a[2][4];
            ldsm_x4(a[0][0], a[0][1], a[0][2], a[0][3], qsb + aoff + ks * 2);
            ldsm_x4(a[1][0], a[1][1], a[1][2], a[1][3], qsb + aoff + 16 * FSTRB + ks * 2);
#pragma unroll
            for (int pr = 0; pr < 2; pr++) {
                uint32_t b0, b1, b2, b3;
                ldsm_x4(b0, b1, b2, b3, ksb + boff + (uint32_t)pr * 16 * FSTRB + ks * 2);
                mma_f16(s[0][2 * pr],     a[0][0], a[0][1], a[0][2], a[0][3], b0, b1);
                mma_f16(s[1][2 * pr],     a[1][0], a[1][1], a[1][2], a[1][3], b0, b1);
                mma_f16(s[0][2 * pr + 1], a[0][0], a[0][1], a[0][2], a[0][3], b2, b3);
                mma_f16(s[1][2 * pr + 1], a[1][0], a[1][1], a[1][2], a[1][3], b2, b3);
            }
        }
        __syncthreads();

        if (j + 1 < nj) {
            const __half* kb = Kbase + (size_t)((j + 1) * 128) * KVW;
#pragma unroll
            for (int it = 0; it < 8; it++) {
                const int r = lr8 + 16 * it;
                CP16(ksb + r * FSTRB + lc8 * 2, kb + (size_t)r * KVW + lc8);
            }
        }
        CPCOMMIT();

        if (j == nj - 1) {
            const int col0 = j * 128;
            const int row0 = qi * 64;
#pragma unroll
            for (int mt = 0; mt < 2; mt++)
#pragma unroll
                for (int nt = 0; nt < 4; nt++) {
                    const int colb = col0 + wn * 32 + nt * 8 + 2 * ak;
#pragma unroll
                    for (int cc = 0; cc < 4; cc++) {
                        const int row_g = row0 + wm * 32 + mt * 16 + ar + (cc >> 1) * 8;
                        const int col_g = colb + (cc & 1);
                        if (col_g > row_g) s[mt][nt][cc] = -1e30f;
                    }
                }
        }

#pragma unroll
        for (int mt = 0; mt < 2; mt++) {
#pragma unroll
            for (int nt = 0; nt < 4; nt++) {
                const int colb = wn * 32 + nt * 8 + 2 * ak;
                float p0 = exp2poly(fmaf(s[mt][nt][0], C, -BIAS));
                float p1 = exp2poly(fmaf(s[mt][nt][1], C, -BIAS));
                float p2, p3;
                if (nt < 2) {
                    p2 = exp2poly(fmaf(s[mt][nt][2], C, -BIAS));
                    p3 = (nt == 0) ? exp2poly(fmaf(s[mt][nt][3], C, -BIAS))
                                   : ex2(fmaf(s[mt][nt][3], C, -BIAS));
                } else {
                    p2 = ex2(fmaf(s[mt][nt][2], C, -BIAS));
                    p3 = ex2(fmaf(s[mt][nt][3], C, -BIAS));
                }
                l_st[mt][0] += p0 + p1;
                l_st[mt][1] += p2 + p3;
                const int r0 = wm * 32 + mt * 16 + ar;
                *(__half2*)&Ps[r0][colb]     = fh2(p0, p1);
                *(__half2*)&Ps[r0 + 8][colb] = fh2(p2, p3);
            }
        }
        CPWAIT(1);
        __syncthreads();

#pragma unroll
        for (int ks = 0; ks < 128; ks += 16) {
            uint32_t a[2][4];
            ldsm_x4(a[0][0], a[0][1], a[0][2], a[0][3], psb + aoff + ks * 2);
            ldsm_x4(a[1][0], a[1][1], a[1][2], a[1][3], psb + aoff + 16 * FSTRB + ks * 2);
#pragma unroll
            for (int half_n = 0; half_n < 2; half_n++) {
                uint32_t b0, b1, b2, b3;
                ldsm_x4t(b0, b1, b2, b3, vsb + voff + (uint32_t)ks * FSTRB + half_n * 32);
                mma_f16(o[0][2 * half_n],     a[0][0], a[0][1], a[0][2], a[0][3], b0, b1);
                mma_f16(o[1][2 * half_n],     a[1][0], a[1][1], a[1][2], a[1][3], b0, b1);
                mma_f16(o[0][2 * half_n + 1], a[0][0], a[0][1], a[0][2], a[0][3], b2, b3);
                mma_f16(o[1][2 * half_n + 1], a[1][0], a[1][1], a[1][2], a[1][3], b2, b3);
            }
        }
        __syncthreads();

        if (j + 1 < nj) {
            const __half* vb = Vbase + (size_t)((j + 1) * 128) * KVW;
#pragma unroll
            for (int it = 0; it < 8; it++) {
                const int r = lr8 + 16 * it;
                CP16(vsb + r * FSTRB + lc8 * 2, vb + (size_t)r * KVW + lc8);
            }
        }
        CPCOMMIT();
    }

#pragma unroll
    for (int mt = 0; mt < 2; mt++) {
        l_st[mt][0] += __shfl_xor_sync(0xffffffffu, l_st[mt][0], 1);
        l_st[mt][0] += __shfl_xor_sync(0xffffffffu, l_st[mt][0], 2);
        l_st[mt][1] += __shfl_xor_sync(0xffffffffu, l_st[mt][1], 1);
        l_st[mt][1] += __shfl_xor_sync(0xffffffffu, l_st[mt][1], 2);
        if (ak == 0) {
            redsum[wn][wm * 32 + mt * 16 + ar]     = l_st[mt][0];
            redsum[wn][wm * 32 + mt * 16 + ar + 8] = l_st[mt][1];
        }
    }
    __syncthreads();

#pragma unroll
    for (int mt = 0; mt < 2; mt++) {
        const int r0 = wm * 32 + mt * 16 + ar;
        const float l0 = (redsum[0][r0] + redsum[1][r0]) + (redsum[2][r0] + redsum[3][r0]);
        const float l1 = (redsum[0][r0 + 8] + redsum[1][r0 + 8]) + (redsum[2][r0 + 8] + redsum[3][r0 + 8]);
        const float i0 = 1.f / l0;
        const float i1 = 1.f / l1;
        __half* c0p = Ctx + (size_t)(qi * 64 + r0) * HID + h * DHEAD;
        __half* c1p = c0p + 8 * HID;
#pragma unroll
        for (int nt = 0; nt < 4; nt++) {
            const int cb = wn * 32 + nt * 8 + 2 * ak;
            *(__half2*)(c0p + cb) = fh2(o[mt][nt][0] * i0, o[mt][nt][1] * i0);
            *(__half2*)(c1p + cb) = fh2(o[mt][nt][2] * i1, o[mt][nt][3] * i1);
        }
    }
}

// ---------------------------------------------------------------------------
// Per-(s,kvhead) RMSNorm + RoPE for K, in place on fp16.
// 256-thread blocks, 2 sequence rows per block.
// ---------------------------------------------------------------------------
__global__ __launch_bounds__(256) void k_normrope_h(
    __half* __restrict__ X, int rowstride,
    const float* __restrict__ sin_t, const float* __restrict__ cos_t,
    const float* __restrict__ w)
{
    const int sr = threadIdx.x >> 7;          // 0..1 sub-row
    const int s  = blockIdx.x * 2 + sr;
    const int h  = blockIdx.y;
    const int d  = threadIdx.x & 127;
    __half* row = X + (size_t)s * rowstride + h * DHEAD;
    float v = __half2float(row[d]);
    float ss = v * v;
#pragma unroll
    for (int o = 16; o > 0; o >>= 1) ss += __shfl_xor_sync(0xffffffffu, ss, o);
    __shared__ float wsum[2][4];
    if ((d & 31) == 0) wsum[sr][d >> 5] = ss;
    __syncthreads();
    float tot = wsum[sr][0] + wsum[sr][1] + wsum[sr][2] + wsum[sr][3];
    float inv = rsqrtf(tot * (1.0f / 128.0f) + 1.1920928955078125e-07f);
    __shared__ float xn[2][128];
    float xv = v * inv * w[d];
    xn[sr][d] = xv;
    __syncthreads();
    float rot = (d < 64) ? -xn[sr][d + 64] : xn[sr][d - 64];
    row[d] = __float2half(cos_t[s * DHEAD + d] * xv + sin_t[s * DHEAD + d] * rot);
}

// ---------------------------------------------------------------------------
// Launch
// ---------------------------------------------------------------------------
extern "C" void kernel_launch(void* const* d_in, const int* in_sizes, int n_in,
                              void* d_out, int out_size)
{
    (void)in_sizes; (void)n_in; (void)out_size;
    const float* x     = (const float*)d_in[0];
    const float* sin_t = (const float*)d_in[1];
    const float* cos_t = (const float*)d_in[2];
    const float* wq    = (const float*)d_in[4];
    const float* wk    = (const float*)d_in[5];
    const float* wv    = (const float*)d_in[6];
    const float* wo    = (const float*)d_in[7];
    const float* qnw   = (const float*)d_in[8];
    const float* knw   = (const float*)d_in[9];
    float* out = (float*)d_out;

    __half *xh, *wqh, *wkh, *wvh, *woh, *qh, *kh, *vh, *ctxh;
    cudaGetSymbolAddress((void**)&xh,   g_xh);
    cudaGetSymbolAddress((void**)&wqh,  g_wqh);
    cudaGetSymbolAddress((void**)&wkh,  g_wkh);
    cudaGetSymbolAddress((void**)&wvh,  g_wvh);
    cudaGetSymbolAddress((void**)&woh,  g_woh);
    cudaGetSymbolAddress((void**)&qh,   g_qh);
    cudaGetSymbolAddress((void**)&kh,   g_kh);
    cudaGetSymbolAddress((void**)&vh,   g_vh);
    cudaGetSymbolAddress((void**)&ctxh, g_ctxh);

    cudaFuncSetAttribute(k_flash, cudaFuncAttributeMaxDynamicSharedMemorySize, FLASH_SMEM);

    // One fused fp32 -> fp16 conversion launch (16 elems/thread)
    k_cvt_all<<<3584, 256>>>(x, wq, wk, wv, wo);

    // Fused QKV projection (fp16 in/out; frozen 4-stage body)
    k_gemm_qkv<<<dim3((HID + 2 * KVW) / 128, SEQ / 128), 256>>>(xh, wqh, wkh, wvh, qh, kh, vh);

    // RMSNorm + RoPE for K (2 rows per block)
    k_normrope_h<<<dim3(SEQ / 2, NKVH), 256>>>(kh, KVW, sin_t, cos_t, knw);

    // Fused flash attention (frozen R14)
    k_flash<<<512, 256, FLASH_SMEM>>>(qh, kh, vh, ctxh, sin_t, cos_t, qnw);

    // Output projection (fp16 in, fp32 out)
    k_gemm_o<<<dim3(HID / 128, SEQ / 128), 256>>>(ctxh, woh, out);
}

// round 17
// speedup vs baseline: 1.2046x; 1.0112x over previous
#include <cuda_runtime.h>
#include <cuda_fp16.h>
#include <math.h>
#include <stddef.h>
#include <stdint.h>

// Problem constants (B=1)
#define SEQ   2048
#define HID   2048
#define NHEADS 16
#define NKVH   4
#define DHEAD  128
#define KVW   (NKVH * DHEAD)      // 512
#define GQA_REP (NHEADS / NKVH)   // 4

// fp16 scratch
__device__ __half g_xh [SEQ * HID];
__device__ __half g_wqh[HID * HID];
__device__ __half g_wkh[KVW * HID];
__device__ __half g_wvh[KVW * HID];
__device__ __half g_woh[HID * HID];
__device__ __half g_qh [SEQ * HID];
__device__ __half g_kh [SEQ * KVW];
__device__ __half g_vh [SEQ * KVW];
__device__ __half g_ctxh[SEQ * HID];

// ---------------------------------------------------------------------------
// helpers
// ---------------------------------------------------------------------------
__device__ __forceinline__ float ex2(float x) {
    float y;
    asm("ex2.approx.ftz.f32 %0, %1;" : "=f"(y) : "f"(x));
    return y;
}
__device__ __forceinline__ float exp2poly(float x) {
    const float MAGIC = 12582912.f;
    float t = fmaxf(x, -126.f);
    float r = t + MAGIC;
    float n = r - MAGIC;
    float f = t - n;
    float p = 1.3333558146e-3f;
    p = fmaf(p, f, 9.6181291076e-3f);
    p = fmaf(p, f, 5.5504108664e-2f);
    p = fmaf(p, f, 2.4022650696e-1f);
    p = fmaf(p, f, 6.9314718056e-1f);
    p = fmaf(p, f, 1.0f);
    int sb = (__float_as_int(r) << 23) + (127 << 23);
    return p * __int_as_float(sb);
}
__device__ __forceinline__ void mma_f16(float c[4],
                                        uint32_t a0, uint32_t a1, uint32_t a2, uint32_t a3,
                                        uint32_t b0, uint32_t b1) {
    asm volatile(
        "mma.sync.aligned.m16n8k16.row.col.f32.f16.f16.f32 "
        "{%0,%1,%2,%3}, {%4,%5,%6,%7}, {%8,%9}, {%0,%1,%2,%3};"
        : "+f"(c[0]), "+f"(c[1]), "+f"(c[2]), "+f"(c[3])
        : "r"(a0), "r"(a1), "r"(a2), "r"(a3), "r"(b0), "r"(b1));
}
__device__ __forceinline__ void ldsm_x4(uint32_t& r0, uint32_t& r1, uint32_t& r2, uint32_t& r3,
                                        uint32_t addr) {
    asm volatile("ldmatrix.sync.aligned.m8n8.x4.shared.b16 {%0,%1,%2,%3}, [%4];"
                 : "=r"(r0), "=r"(r1), "=r"(r2), "=r"(r3) : "r"(addr));
}
__device__ __forceinline__ void ldsm_x4t(uint32_t& r0, uint32_t& r1, uint32_t& r2, uint32_t& r3,
                                         uint32_t addr) {
    asm volatile("ldmatrix.sync.aligned.m8n8.x4.trans.shared.b16 {%0,%1,%2,%3}, [%4];"
                 : "=r"(r0), "=r"(r1), "=r"(r2), "=r"(r3) : "r"(addr));
}
__device__ __forceinline__ uint32_t ldsmA_off(int lane, int stride_bytes) {
    return (uint32_t)((lane & 15) * stride_bytes + (((lane >> 4) & 1) << 4));
}
__device__ __forceinline__ uint32_t ldsmB_off(int lane, int stride_bytes) {
    int row = (lane & 7) + ((lane & 16) >> 1);
    return (uint32_t)(row * stride_bytes + (((lane >> 3) & 1) << 4));
}
__device__ __forceinline__ __half2 fh2(float x, float y) { return __floats2half2_rn(x, y); }

#define CP16(s, g)  asm volatile("cp.async.cg.shared.global [%0], [%1], 16;" :: "r"(s), "l"(g))
#define CPCOMMIT()  asm volatile("cp.async.commit_group;")
#define CPWAIT(n)   asm volatile("cp.async.wait_group " #n ";")

// ---------------------------------------------------------------------------
// Fused fp32 -> fp16 convert, 16 elems/thread (one launch, region dispatch)
// ---------------------------------------------------------------------------
__global__ __launch_bounds__(256) void k_cvt_all(
    const float* __restrict__ x,  const float* __restrict__ wq,
    const float* __restrict__ wk, const float* __restrict__ wv,
    const float* __restrict__ wo)
{
    const int b = blockIdx.x;
    const float* s; __half* d; int base;
    if (b < 1024)      { s = x;  d = g_xh;  base = b; }
    else if (b < 2048) { s = wq; d = g_wqh; base = b - 1024; }
    else if (b < 2304) { s = wk; d = g_wkh; base = b - 2048; }
    else if (b < 2560) { s = wv; d = g_wvh; base = b - 2304; }
    else               { s = wo; d = g_woh; base = b - 2560; }
    const int i = (base * 256 + threadIdx.x) * 16;
#pragma unroll
    for (int q = 0; q < 2; q++) {
        float4 a = *(const float4*)(s + i + q * 8);
        float4 c = *(const float4*)(s + i + q * 8 + 4);
        __half2 h0 = fh2(a.x, a.y), h1 = fh2(a.z, a.w);
        __half2 h2 = fh2(c.x, c.y), h3 = fh2(c.z, c.w);
        uint4 u;
        u.x = *(uint32_t*)&h0; u.y = *(uint32_t*)&h1;
        u.z = *(uint32_t*)&h2; u.w = *(uint32_t*)&h3;
        *(uint4*)(d + i + q * 8) = u;
    }
}

// ---------------------------------------------------------------------------
// TN GEMM (fp16 in via cp.async 4-stage pipeline): C = A[M,K]*B[N,K]^T
// (frozen body)
// ---------------------------------------------------------------------------
#define GSTR  24
#define GSTRB (GSTR * 2)
#define NSTG  4
#define STGB  (128 * GSTRB)

template <bool HALF_OUT>
__device__ __forceinline__ void gemm_tn_f16(
    const __half* __restrict__ A, int lda,
    const __half* __restrict__ B, int ldb,
    void* __restrict__ Cv, int ldc,
    int K, int bm, int bn)
{
    __shared__ __half As[NSTG][128][GSTR];
    __shared__ __half Bs[NSTG][128][GSTR];
    const int tid  = threadIdx.x;
    const int lane = tid & 31;
    const int w    = tid >> 5;
    const int wm   = w >> 1;
    const int wn   = w & 1;

    float acc[2][8][4];
#pragma unroll
    for (int mt = 0; mt < 2; mt++)
#pragma unroll
        for (int nt = 0; nt < 8; nt++)
#pragma unroll
            for (int i = 0; i < 4; i++) acc[mt][nt][i] = 0.f;

    const int lrow = tid >> 1;
    const int lch  = (tid & 1) << 3;
    const __half* Ag = A + (size_t)(bm + lrow) * lda + lch;
    const __half* Bg = B + (size_t)(bn + lrow) * ldb + lch;
    const uint32_t sA = (uint32_t)__cvta_generic_to_shared(&As[0][0][0]) + lrow * GSTRB + lch * 2;
    const uint32_t sB = (uint32_t)__cvta_generic_to_shared(&Bs[0][0][0]) + lrow * GSTRB + lch * 2;

    const uint32_t asb = (uint32_t)__cvta_generic_to_shared(&As[0][0][0]);
    const uint32_t bsb = (uint32_t)__cvta_generic_to_shared(&Bs[0][0][0]);
    const uint32_t aoff = ldsmA_off(lane, GSTRB) + (uint32_t)(wm * 32) * GSTRB;
    const uint32_t boff = ldsmB_off(lane, GSTRB) + (uint32_t)(wn * 64) * GSTRB;

    const int nch = K >> 4;
#pragma unroll
    for (int s = 0; s < NSTG - 1; s++) {
        CP16(sA + s * STGB, Ag + s * 16);
        CP16(sB + s * STGB, Bg + s * 16);
        CPCOMMIT();
    }

    for (int i = 0; i < nch; i++) {
        CPWAIT(2);
        __syncthreads();
        const int nc = i + NSTG - 1;
        if (nc < nch) {
            const uint32_t stg = (uint32_t)(nc & (NSTG - 1)) * STGB;
            CP16(sA + stg, Ag + nc * 16);
            CP16(sB + stg, Bg + nc * 16);
        }
        CPCOMMIT();

        const uint32_t st = (uint32_t)(i & (NSTG - 1)) * STGB;
        const uint32_t ab = asb + st + aoff;
        const uint32_t bb = bsb + st + boff;
        uint32_t a[2][4];
        ldsm_x4(a[0][0], a[0][1], a[0][2], a[0][3], ab);
        ldsm_x4(a[1][0], a[1][1], a[1][2], a[1][3], ab + 16 * GSTRB);
#pragma unroll
        for (int pr = 0; pr < 4; pr++) {
            uint32_t b0, b1, b2, b3;
            ldsm_x4(b0, b1, b2, b3, bb + (uint32_t)pr * 16 * GSTRB);
            mma_f16(acc[0][2 * pr],     a[0][0], a[0][1], a[0][2], a[0][3], b0, b1);
            mma_f16(acc[1][2 * pr],     a[1][0], a[1][1], a[1][2], a[1][3], b0, b1);
            mma_f16(acc[0][2 * pr + 1], a[0][0], a[0][1], a[0][2], a[0][3], b2, b3);
            mma_f16(acc[1][2 * pr + 1], a[1][0], a[1][1], a[1][2], a[1][3], b2, b3);
        }
    }

    const int ar = lane >> 2;
    const int ak = lane & 3;
#pragma unroll
    for (int mt = 0; mt < 2; mt++) {
        const int r0 = bm + wm * 32 + mt * 16 + ar;
#pragma unroll
        for (int nt = 0; nt < 8; nt++) {
            const int cidx = bn + wn * 64 + nt * 8 + 2 * ak;
            if (HALF_OUT) {
                __half* C = (__half*)Cv;
                *(__half2*)(C + (size_t)r0 * ldc + cidx)       = fh2(acc[mt][nt][0], acc[mt][nt][1]);
                *(__half2*)(C + (size_t)(r0 + 8) * ldc + cidx) = fh2(acc[mt][nt][2], acc[mt][nt][3]);
            } else {
                float* C = (float*)Cv;
                *(float2*)(C + (size_t)r0 * ldc + cidx)       = make_float2(acc[mt][nt][0], acc[mt][nt][1]);
                *(float2*)(C + (size_t)(r0 + 8) * ldc + cidx) = make_float2(acc[mt][nt][2], acc[mt][nt][3]);
            }
        }
    }
}

__global__ __launch_bounds__(256, 2) void k_gemm_qkv(
    const __half* __restrict__ x,
    const __half* __restrict__ wq, const __half* __restrict__ wk,
    const __half* __restrict__ wv,
    __half* __restrict__ q, __half* __restrict__ k, __half* __restrict__ v)
{
    const int bnx = blockIdx.x * 128;
    const __half* B; __half* C; int ldc; int bn;
    if (bnx < HID)            { B = wq; C = q; ldc = HID; bn = bnx; }
    else if (bnx < HID + KVW) { B = wk; C = k; ldc = KVW; bn = bnx - HID; }
    else                      { B = wv; C = v; ldc = KVW; bn = bnx - HID - KVW; }
    gemm_tn_f16<true>(x, HID, B, HID, C, ldc, HID, blockIdx.y * 128, bn);
}

__global__ __launch_bounds__(256, 2) void k_gemm_o(
    const __half* __restrict__ A, const __half* __restrict__ B,
    float* __restrict__ C)
{
    gemm_tn_f16<false>(A, HID, B, HID, C, HID, HID, blockIdx.y * 128, blockIdx.x * 128);
}

// ---------------------------------------------------------------------------
// Fused flash attention (R14 internals, LPT-balanced schedule):
// grid 288 = 16 heads x 18 CTAs. Per head:
//   p=0..3 : single q-block qi = 31-p            (work 16,16,15,15)
//   p=4..17: pair (27-2k-s, 2k+1-s), k=(p-4)>>1, s=(p-4)&1  (work 15 each)
// -> every CTA <= 16 work units; 288 CTAs ~= 296 slots: one balanced wave.
// ---------------------------------------------------------------------------
#define FSTR  136
#define FSTRB (FSTR * 2)
#define QS_OFF   0
#define KS_OFF   (64 * FSTRB)
#define VS_OFF   (KS_OFF + 128 * FSTRB)
#define PS_OFF   (VS_OFF + 128 * FSTRB)
#define RSM_OFF  (PS_OFF + 64 * FSTRB)
#define FLASH_SMEM (RSM_OFF + 4 * 64 * 4)        // 105472

__global__ __launch_bounds__(256, 2) void k_flash(
    const __half* __restrict__ Qg, const __half* __restrict__ Kg,
    const __half* __restrict__ Vg, __half* __restrict__ Ctx,
    const float* __restrict__ sin_t, const float* __restrict__ cos_t,
    const float* __restrict__ qnw)
{
    extern __shared__ char smem[];
    __half (*Qs)[FSTR]  = (__half(*)[FSTR])(smem + QS_OFF);
    __half (*Ps)[FSTR]  = (__half(*)[FSTR])(smem + PS_OFF);
    float (*redsum)[64] = (float(*)[64])(smem + RSM_OFF);

    const int bid = blockIdx.x;
    const int h   = bid & 15;
    const int p   = bid >> 4;                 // 0..17
    const int kvh = h >> 2;

    int npass, q0, q1;
    if (p < 4) { npass = 1; q0 = 31 - p; q1 = 0; }
    else {
        const int k = (p - 4) >> 1, sb = (p - 4) & 1;
        npass = 2; q0 = 27 - 2 * k - sb; q1 = 2 * k + 1 - sb;
    }

    const int tid  = threadIdx.x;
    const int lane = tid & 31;
    const int w    = tid >> 5;
    const int wm   = w >> 2;
    const int wn   = w & 3;
    const int ar   = lane >> 2;
    const int ak   = lane & 3;
    const float C  = (float)(0.08838834764831843 * 1.4426950408889634);
    const float BIAS = 8.0f;

    const uint32_t qsb = (uint32_t)__cvta_generic_to_shared(&Qs[0][0]);
    const uint32_t ksb = (uint32_t)__cvta_generic_to_shared(smem + KS_OFF);
    const uint32_t vsb = (uint32_t)__cvta_generic_to_shared(smem + VS_OFF);
    const uint32_t psb = (uint32_t)__cvta_generic_to_shared(smem + PS_OFF);
    const uint32_t aoff = ldsmA_off(lane, FSTRB) + (uint32_t)(wm * 32) * FSTRB;
    const uint32_t boff = ldsmB_off(lane, FSTRB) + (uint32_t)(wn * 32) * FSTRB;
    const uint32_t voff = (uint32_t)(((lane & 7) + ((lane >> 3) & 1) * 8) * FSTRB
                                     + (((lane >> 4) & 1) * 8 + wn * 32) * 2);

    const __half* Kbase = Kg + kvh * DHEAD;
    const __half* Vbase = Vg + kvh * DHEAD;
    const int lr8 = tid >> 4;
    const int lc8 = (tid & 15) << 3;

#pragma unroll 1
    for (int pass = 0; pass < npass; pass++) {
        const int qi = pass ? q1 : q0;

        // Q tile [64 x 128]: fp16 q -> fp32 RMSNorm + RoPE -> fp16 smem
        {
            const int r  = tid >> 2;
            const int c0 = (tid & 3) << 2;
            const int s  = qi * 64 + r;
            const __half* qp = Qg + (size_t)s * HID + h * DHEAD;
            float4 qa[8];
            float ss = 0.f;
#pragma unroll
            for (int i = 0; i < 8; i++) {
                const __half2* ph = (const __half2*)(qp + c0 + 16 * i);
                float2 f01 = __half22float2(ph[0]);
                float2 f23 = __half22float2(ph[1]);
                qa[i] = make_float4(f01.x, f01.y, f23.x, f23.y);
                ss += qa[i].x * qa[i].x + qa[i].y * qa[i].y + qa[i].z * qa[i].z + qa[i].w * qa[i].w;
            }
            ss += __shfl_xor_sync(0xffffffffu, ss, 1);
            ss += __shfl_xor_sync(0xffffffffu, ss, 2);
            const float inv = rsqrtf(ss * (1.0f / 128.0f) + 1.1920928955078125e-07f);
            float4 xn[8];
#pragma unroll
            for (int i = 0; i < 8; i++) {
                float4 wv4 = *(const float4*)(qnw + c0 + 16 * i);
                xn[i] = make_float4(qa[i].x * inv * wv4.x, qa[i].y * inv * wv4.y,
                                    qa[i].z * inv * wv4.z, qa[i].w * inv * wv4.w);
            }
            const float* sp = sin_t + (size_t)s * DHEAD;
            const float* cp = cos_t + (size_t)s * DHEAD;
#pragma unroll
            for (int i = 0; i < 8; i++) {
                const int c = c0 + 16 * i;
                float4 s4 = *(const float4*)(sp + c);
                float4 c4 = *(const float4*)(cp + c);
                float4 rot = (i < 4)
                    ? make_float4(-xn[i + 4].x, -xn[i + 4].y, -xn[i + 4].z, -xn[i + 4].w)
                    : xn[i - 4];
                *(__half2*)&Qs[r][c]     = fh2(c4.x * xn[i].x + s4.x * rot.x,
                                               c4.y * xn[i].y + s4.y * rot.y);
                *(__half2*)&Qs[r][c + 2] = fh2(c4.z * xn[i].z + s4.z * rot.z,
                                               c4.w * xn[i].w + s4.w * rot.w);
            }
        }

        float o[2][4][4];
        float l_st[2][2];
#pragma unroll
        for (int mt = 0; mt < 2; mt++) {
#pragma unroll
            for (int nt = 0; nt < 4; nt++)
#pragma unroll
                for (int c = 0; c < 4; c++) o[mt][nt][c] = 0.f;
            l_st[mt][0] = l_st[mt][1] = 0.f;
        }

        const int nj = (qi >> 1) + 1;

        // prologue: K(0) then V(0), separate groups
        {
#pragma unroll
            for (int it = 0; it < 8; it++) {
                const int r = lr8 + 16 * it;
                CP16(ksb + r * FSTRB + lc8 * 2, Kbase + (size_t)r * KVW + lc8);
            }
            CPCOMMIT();
#pragma unroll
            for (int it = 0; it < 8; it++) {
                const int r = lr8 + 16 * it;
                CP16(vsb + r * FSTRB + lc8 * 2, Vbase + (size_t)r * KVW + lc8);
            }
            CPCOMMIT();
        }

        for (int j = 0; j < nj; j++) {
            CPWAIT(1);
            __syncthreads();

            float s[2][4][4];
#pragma unroll
            for (int mt = 0; mt < 2; mt++)
#pragma unroll
                for (int nt = 0; nt < 4; nt++)
#pragma unroll
                    for (int c = 0; c < 4; c++) s[mt][nt][c] = 0.f;
#pragma unroll
            for (int ks = 0; ks < 128; ks += 16) {
                uint32_t a[2][4];
                ldsm_x4(a[0][0], a[0][1], a[0][2], a[0][3], qsb + aoff + ks * 2);
                ldsm_x4(a[1][0], a[1][1], a[1][2], a[1][3], qsb + aoff + 16 * FSTRB + ks * 2);
#pragma unroll
                for (int pr = 0; pr < 2; pr++) {
                    uint32_t b0, b1, b2, b3;
                    ldsm_x4(b0, b1, b2, b3, ksb + boff + (uint32_t)pr * 16 * FSTRB + ks * 2);
                    mma_f16(s[0][2 * pr],     a[0][0], a[0][1], a[0][2], a[0][3], b0, b1);
                    mma_f16(s[1][2 * pr],     a[1][0], a[1][1], a[1][2], a[1][3], b0, b1);
                    mma_f16(s[0][2 * pr + 1], a[0][0], a[0][1], a[0][2], a[0][3], b2, b3);
                    mma_f16(s[1][2 * pr + 1], a[1][0], a[1][1], a[1][2], a[1][3], b2, b3);
                }
            }
            __syncthreads();

            if (j + 1 < nj) {
                const __half* kb = Kbase + (size_t)((j + 1) * 128) * KVW;
#pragma unroll
                for (int it = 0; it < 8; it++) {
                    const int r = lr8 + 16 * it;
                    CP16(ksb + r * FSTRB + lc8 * 2, kb + (size_t)r * KVW + lc8);
                }
            }
            CPCOMMIT();

            if (j == nj - 1) {
                const int col0 = j * 128;
                const int row0 = qi * 64;
#pragma unroll
                for (int mt = 0; mt < 2; mt++)
#pragma unroll
                    for (int nt = 0; nt < 4; nt++) {
                        const int colb = col0 + wn * 32 + nt * 8 + 2 * ak;
#pragma unroll
                        for (int cc = 0; cc < 4; cc++) {
                            const int row_g = row0 + wm * 32 + mt * 16 + ar + (cc >> 1) * 8;
                            const int col_g = colb + (cc & 1);
                            if (col_g > row_g) s[mt][nt][cc] = -1e30f;
                        }
                    }
            }

#pragma unroll
            for (int mt = 0; mt < 2; mt++) {
#pragma unroll
                for (int nt = 0; nt < 4; nt++) {
                    const int colb = wn * 32 + nt * 8 + 2 * ak;
                    float p0 = exp2poly(fmaf(s[mt][nt][0], C, -BIAS));
                    float p1 = exp2poly(fmaf(s[mt][nt][1], C, -BIAS));
                    float p2, p3;
                    if (nt < 2) {
                        p2 = exp2poly(fmaf(s[mt][nt][2], C, -BIAS));
                        p3 = (nt == 0) ? exp2poly(fmaf(s[mt][nt][3], C, -BIAS))
                                       : ex2(fmaf(s[mt][nt][3], C, -BIAS));
                    } else {
                        p2 = ex2(fmaf(s[mt][nt][2], C, -BIAS));
                        p3 = ex2(fmaf(s[mt][nt][3], C, -BIAS));
                    }
                    l_st[mt][0] += p0 + p1;
                    l_st[mt][1] += p2 + p3;
                    const int r0 = wm * 32 + mt * 16 + ar;
                    *(__half2*)&Ps[r0][colb]     = fh2(p0, p1);
                    *(__half2*)&Ps[r0 + 8][colb] = fh2(p2, p3);
                }
            }
            CPWAIT(1);
            __syncthreads();

#pragma unroll
            for (int ks = 0; ks < 128; ks += 16) {
                uint32_t a[2][4];
                ldsm_x4(a[0][0], a[0][1], a[0][2], a[0][3], psb + aoff + ks * 2);
                ldsm_x4(a[1][0], a[1][1], a[1][2], a[1][3], psb + aoff + 16 * FSTRB + ks * 2);
#pragma unroll
                for (int half_n = 0; half_n < 2; half_n++) {
                    uint32_t b0, b1, b2, b3;
                    ldsm_x4t(b0, b1, b2, b3, vsb + voff + (uint32_t)ks * FSTRB + half_n * 32);
                    mma_f16(o[0][2 * half_n],     a[0][0], a[0][1], a[0][2], a[0][3], b0, b1);
                    mma_f16(o[1][2 * half_n],     a[1][0], a[1][1], a[1][2], a[1][3], b0, b1);
                    mma_f16(o[0][2 * half_n + 1], a[0][0], a[0][1], a[0][2], a[0][3], b2, b3);
                    mma_f16(o[1][2 * half_n + 1], a[1][0], a[1][1], a[1][2], a[1][3], b2, b3);
                }
            }
            __syncthreads();

            if (j + 1 < nj) {
                const __half* vb = Vbase + (size_t)((j + 1) * 128) * KVW;
#pragma unroll
                for (int it = 0; it < 8; it++) {
                    const int r = lr8 + 16 * it;
                    CP16(vsb + r * FSTRB + lc8 * 2, vb + (size_t)r * KVW + lc8);
                }
            }
            CPCOMMIT();
        }

        // final l reduction + epilogue for this pass
#pragma unroll
        for (int mt = 0; mt < 2; mt++) {
            l_st[mt][0] += __shfl_xor_sync(0xffffffffu, l_st[mt][0], 1);
            l_st[mt][0] += __shfl_xor_sync(0xffffffffu, l_st[mt][0], 2);
            l_st[mt][1] += __shfl_xor_sync(0xffffffffu, l_st[mt][1], 1);
            l_st[mt][1] += __shfl_xor_sync(0xffffffffu, l_st[mt][1], 2);
            if (ak == 0) {
                redsum[wn][wm * 32 + mt * 16 + ar]     = l_st[mt][0];
                redsum[wn][wm * 32 + mt * 16 + ar + 8] = l_st[mt][1];
            }
        }
        __syncthreads();

#pragma unroll
        for (int mt = 0; mt < 2; mt++) {
            const int r0 = wm * 32 + mt * 16 + ar;
            const float l0 = (redsum[0][r0] + redsum[1][r0]) + (redsum[2][r0] + redsum[3][r0]);
            const float l1 = (redsum[0][r0 + 8] + redsum[1][r0 + 8]) + (redsum[2][r0 + 8] + redsum[3][r0 + 8]);
            const float i0 = 1.f / l0;
            const float i1 = 1.f / l1;
            __half* c0p = Ctx + (size_t)(qi * 64 + r0) * HID + h * DHEAD;
            __half* c1p = c0p + 8 * HID;
#pragma unroll
            for (int nt = 0; nt < 4; nt++) {
                const int cb = wn * 32 + nt * 8 + 2 * ak;
                *(__half2*)(c0p + cb) = fh2(o[mt][nt][0] * i0, o[mt][nt][1] * i0);
                *(__half2*)(c1p + cb) = fh2(o[mt][nt][2] * i1, o[mt][nt][3] * i1);
            }
        }
        __syncthreads();   // smem (Qs/redsum) safe for next pass
    }
}

// ---------------------------------------------------------------------------
// Per-(s,kvhead) RMSNorm + RoPE for K, in place on fp16. 2 rows per block.
// ---------------------------------------------------------------------------
__global__ __launch_bounds__(256) void k_normrope_h(
    __half* __restrict__ X, int rowstride,
    const float* __restrict__ sin_t, const float* __restrict__ cos_t,
    const float* __restrict__ w)
{
    const int sr = threadIdx.x >> 7;
    const int s  = blockIdx.x * 2 + sr;
    const int h  = blockIdx.y;
    const int d  = threadIdx.x & 127;
    __half* row = X + (size_t)s * rowstride + h * DHEAD;
    float v = __half2float(row[d]);
    float ss = v * v;
#pragma unroll
    for (int o = 16; o > 0; o >>= 1) ss += __shfl_xor_sync(0xffffffffu, ss, o);
    __shared__ float wsum[2][4];
    if ((d & 31) == 0) wsum[sr][d >> 5] = ss;
    __syncthreads();
    float tot = wsum[sr][0] + wsum[sr][1] + wsum[sr][2] + wsum[sr][3];
    float inv = rsqrtf(tot * (1.0f / 128.0f) + 1.1920928955078125e-07f);
    __shared__ float xn[2][128];
    float xv = v * inv * w[d];
    xn[sr][d] = xv;
    __syncthreads();
    float rot = (d < 64) ? -xn[sr][d + 64] : xn[sr][d - 64];
    row[d] = __float2half(cos_t[s * DHEAD + d] * xv + sin_t[s * DHEAD + d] * rot);
}

// ---------------------------------------------------------------------------
// Launch
// ---------------------------------------------------------------------------
extern "C" void kernel_launch(void* const* d_in, const int* in_sizes, int n_in,
                              void* d_out, int out_size)
{
    (void)in_sizes; (void)n_in; (void)out_size;
    const float* x     = (const float*)d_in[0];
    const float* sin_t = (const float*)d_in[1];
    const float* cos_t = (const float*)d_in[2];
    const float* wq    = (const float*)d_in[4];
    const float* wk    = (const float*)d_in[5];
    const float* wv    = (const float*)d_in[6];
    const float* wo    = (const float*)d_in[7];
    const float* qnw   = (const float*)d_in[8];
    const float* knw   = (const float*)d_in[9];
    float* out = (float*)d_out;

    __half *xh, *wqh, *wkh, *wvh, *woh, *qh, *kh, *vh, *ctxh;
    cudaGetSymbolAddress((void**)&xh,   g_xh);
    cudaGetSymbolAddress((void**)&wqh,  g_wqh);
    cudaGetSymbolAddress((void**)&wkh,  g_wkh);
    cudaGetSymbolAddress((void**)&wvh,  g_wvh);
    cudaGetSymbolAddress((void**)&woh,  g_woh);
    cudaGetSymbolAddress((void**)&qh,   g_qh);
    cudaGetSymbolAddress((void**)&kh,   g_kh);
    cudaGetSymbolAddress((void**)&vh,   g_vh);
    cudaGetSymbolAddress((void**)&ctxh, g_ctxh);

    cudaFuncSetAttribute(k_flash, cudaFuncAttributeMaxDynamicSharedMemorySize, FLASH_SMEM);

    // One fused fp32 -> fp16 conversion launch (16 elems/thread)
    k_cvt_all<<<3584, 256>>>(x, wq, wk, wv, wo);

    // Fused QKV projection (frozen 4-stage body)
    k_gemm_qkv<<<dim3((HID + 2 * KVW) / 128, SEQ / 128), 256>>>(xh, wqh, wkh, wvh, qh, kh, vh);

    // RMSNorm + RoPE for K
    k_normrope_h<<<dim3(SEQ / 2, NKVH), 256>>>(kh, KVW, sin_t, cos_t, knw);

    // Fused flash attention: 288 CTAs, LPT-balanced single wave
    k_flash<<<288, 256, FLASH_SMEM>>>(qh, kh, vh, ctxh, sin_t, cos_t, qnw);

    // Output projection (fp16 in, fp32 out)
    k_gemm_o<<<dim3(HID / 128, SEQ / 128), 256>>>(ctxh, woh, out);
}